// round 11
// baseline (speedup 1.0000x reference)
#include <cuda_runtime.h>
#include <cuda_bf16.h>
#include <math.h>
#include <stdint.h>

// Problem constants
#define BATCH 16
#define LSEQ  256
#define DMDL  1024           // dm == di
#define DTOT  68             // dtr + 2*n
#define DTR   64
#define MROWS (BATCH*LSEQ)   // 4096

// ---------------- scratch (device globals; no allocations allowed) ----------
__device__ float g_xz [BATCH*LSEQ*2*DMDL];
__device__ float g_xi [BATCH*LSEQ*DMDL];
__device__ float g_dbl[BATCH*LSEQ*DTOT];
__device__ float g_dt [BATCH*LSEQ*DMDL];
__device__ float g_y  [BATCH*LSEQ*DMDL];
__device__ float g_s  [BATCH*LSEQ*DMDL];
__device__ float g_t  [BATCH*LSEQ*DMDL];
__device__ float g_r  [BATCH*LSEQ*DMDL];
__device__ float g_r2 [BATCH*LSEQ*DMDL];
// packed bf16 hi/lo operand buffers for the big GEMMs
__device__ uint32_t g_Ah[MROWS*(DMDL/2)];      // activations: 4096 x 512 u32
__device__ uint32_t g_Al[MROWS*(DMDL/2)];
__device__ uint32_t g_Bh[(2*DMDL)*(DMDL/2)];   // weights: 2048 x 512 u32
__device__ uint32_t g_Bl[(2*DMDL)*(DMDL/2)];

// ---------------- helpers ----------------------------------------------------
__device__ __forceinline__ float silu_f(float v) {
    return v / (1.0f + expf(-v));
}
__device__ __forceinline__ float softplus_f(float v) {
    return fmaxf(v, 0.0f) + log1pf(expf(-fabsf(v)));
}
__device__ __forceinline__ unsigned pack_bf2(__nv_bfloat16 a, __nv_bfloat16 b) {
    __nv_bfloat162 t(a, b);          // a -> low half, b -> high half
    return *reinterpret_cast<unsigned*>(&t);
}
__device__ __forceinline__ void bf16_split(float x, __nv_bfloat16& h, __nv_bfloat16& l) {
    h = __float2bfloat16_rn(x);
    l = __float2bfloat16_rn(x - __bfloat162float(h));
}
__device__ __forceinline__ void split_pack4(float4 v, uint2& h, uint2& l) {
    __nv_bfloat16 hx, hy, hz, hw, lx, ly, lz, lw;
    bf16_split(v.x, hx, lx);
    bf16_split(v.y, hy, ly);
    bf16_split(v.z, hz, lz);
    bf16_split(v.w, hw, lw);
    h.x = pack_bf2(hx, hy); h.y = pack_bf2(hz, hw);
    l.x = pack_bf2(lx, ly); l.y = pack_bf2(lz, lw);
}
__device__ __forceinline__ void mma_bf16(float* c, const unsigned* a, const unsigned* b) {
    asm volatile(
        "mma.sync.aligned.m16n8k16.row.col.f32.bf16.bf16.f32 "
        "{%0,%1,%2,%3},{%4,%5,%6,%7},{%8,%9},{%0,%1,%2,%3};\n"
        : "+f"(c[0]), "+f"(c[1]), "+f"(c[2]), "+f"(c[3])
        : "r"(a[0]), "r"(a[1]), "r"(a[2]), "r"(a[3]), "r"(b[0]), "r"(b[1]));
}
__device__ __forceinline__ uint32_t smem_u32(const void* p) {
    uint32_t a;
    asm("{ .reg .u64 t; cvta.to.shared.u64 t, %1; cvt.u32.u64 %0, t; }" : "=r"(a) : "l"(p));
    return a;
}
__device__ __forceinline__ void ldsm_x4(unsigned* r, uint32_t addr) {
    asm volatile("ldmatrix.sync.aligned.m8n8.x4.shared.b16 {%0,%1,%2,%3}, [%4];"
                 : "=r"(r[0]), "=r"(r[1]), "=r"(r[2]), "=r"(r[3]) : "r"(addr));
}

// ================== pre-split: fp32 -> packed bf16 hi/lo ======================
// in: L floats (L % 2048 == 0). Each thread: 8 floats -> 4 u32 hi + 4 u32 lo.
__global__ __launch_bounds__(256)
void split_kernel(const float4* __restrict__ in,
                  uint4* __restrict__ hi, uint4* __restrict__ lo)
{
    const size_t i = (size_t)blockIdx.x * 256 + threadIdx.x;
    float4 a = in[2 * i], b = in[2 * i + 1];
    uint2 ha, la, hb, lb;
    split_pack4(a, ha, la);
    split_pack4(b, hb, lb);
    hi[i] = make_uint4(ha.x, ha.y, hb.x, hb.y);
    lo[i] = make_uint4(la.x, la.y, lb.x, lb.y);
}

// ================== 3x-bf16 LDSM GEMM (big BT GEMMs) ==========================
// C[m,n] = epi( sum_k A[m,k]*B[n,k] ) with A,B pre-split hi/lo packed u32
// (u32 = 2 consecutive k as bf16x2). M%128==0, N%128==0, K%16==0.
// EPI: 0 none, 2 silu(v+bias[n])
template<int EPI>
__global__ __launch_bounds__(256, 2)
void bgemm_kernel(const uint32_t* __restrict__ Ah, const uint32_t* __restrict__ Al,
                  const uint32_t* __restrict__ Bh, const uint32_t* __restrict__ Bl,
                  const float* __restrict__ bias,
                  float* __restrict__ C, int ldc, int M, int N, int K)
{
    __shared__ __align__(16) uint32_t SAh[128][12];
    __shared__ __align__(16) uint32_t SAl[128][12];
    __shared__ __align__(16) uint32_t SBh[128][12];
    __shared__ __align__(16) uint32_t SBl[128][12];

    const int ld2 = K >> 1;                 // u32 per row
    const int m0 = blockIdx.y * 128;
    const int n0 = blockIdx.x * 128;
    const int tid = threadIdx.x;
    const int warp = tid >> 5, lane = tid & 31;
    const int wm = warp & 1;                // 2 warps along M
    const int wn = warp >> 1;               // 4 warps along N
    const int g  = lane >> 2;
    const int tg = lane & 3;

    float acc[4][4][4];
    #pragma unroll
    for (int mi = 0; mi < 4; mi++)
        #pragma unroll
        for (int ni = 0; ni < 4; ni++)
            #pragma unroll
            for (int q = 0; q < 4; q++) acc[mi][ni][q] = 0.0f;

    // loader map: thread -> (row, 16B half of the 32-u32... here 8-u32 row)
    const int lrow = tid >> 1;              // 0..127
    const int lhalf = tid & 1;              // 0,1 -> u32 cols 0..3 / 4..7
    const size_t gA = (size_t)(m0 + lrow) * ld2 + lhalf * 4;
    const size_t gB = (size_t)(n0 + lrow) * ld2 + lhalf * 4;

    // ldmatrix base addresses (depend only on lane)
    const uint32_t aAh = smem_u32(&SAh[wm * 64 + (lane & 15)][(lane >> 4) * 4]);
    const uint32_t aAl = smem_u32(&SAl[wm * 64 + (lane & 15)][(lane >> 4) * 4]);
    const int brow = wn * 32 + ((lane >> 4) * 8) + (lane & 7);
    const int bcol = ((lane >> 3) & 1) * 4;
    const uint32_t aBh = smem_u32(&SBh[brow][bcol]);
    const uint32_t aBl = smem_u32(&SBl[brow][bcol]);

    // prologue prefetch (k-tile 0)
    uint4 ra_h = *(const uint4*)(Ah + gA);
    uint4 ra_l = *(const uint4*)(Al + gA);
    uint4 rb_h = *(const uint4*)(Bh + gB);
    uint4 rb_l = *(const uint4*)(Bl + gB);

    int k0 = 0;
    while (true) {
        *(uint4*)&SAh[lrow][lhalf * 4] = ra_h;
        *(uint4*)&SAl[lrow][lhalf * 4] = ra_l;
        *(uint4*)&SBh[lrow][lhalf * 4] = rb_h;
        *(uint4*)&SBl[lrow][lhalf * 4] = rb_l;
        __syncthreads();

        const int kn = k0 + 16;
        const bool more = kn < K;
        if (more) {
            const size_t o = (size_t)(kn >> 1);
            ra_h = *(const uint4*)(Ah + gA + o);
            ra_l = *(const uint4*)(Al + gA + o);
            rb_h = *(const uint4*)(Bh + gB + o);
            rb_l = *(const uint4*)(Bl + gB + o);
        }

        // B fragments: 2 pairs x (hi,lo), each ldmatrix.x4 covers 2 n8-tiles
        unsigned qh[2][4], ql[2][4];
        #pragma unroll
        for (int p = 0; p < 2; p++) {
            ldsm_x4(qh[p], aBh + p * 16 * 48);
            ldsm_x4(ql[p], aBl + p * 16 * 48);
        }
        #pragma unroll
        for (int mi = 0; mi < 4; mi++) {
            unsigned ah[4], al[4];
            ldsm_x4(ah, aAh + mi * 16 * 48);
            ldsm_x4(al, aAl + mi * 16 * 48);
            #pragma unroll
            for (int ni = 0; ni < 4; ni++) {
                const int p = ni >> 1, s = (ni & 1) * 2;
                mma_bf16(acc[mi][ni], ah, &qh[p][s]);   // hi*hi
                mma_bf16(acc[mi][ni], ah, &ql[p][s]);   // hi*lo
                mma_bf16(acc[mi][ni], al, &qh[p][s]);   // lo*hi
            }
        }

        if (!more) break;
        __syncthreads();
        k0 = kn;
    }

    // epilogue
    #pragma unroll
    for (int mi = 0; mi < 4; mi++) {
        const int r = m0 + wm * 64 + mi * 16 + g;
        #pragma unroll
        for (int ni = 0; ni < 4; ni++) {
            const int c = n0 + wn * 32 + ni * 8 + tg * 2;
            float v0 = acc[mi][ni][0];
            float v1 = acc[mi][ni][1];
            float v2 = acc[mi][ni][2];
            float v3 = acc[mi][ni][3];
            if (EPI == 2) {
                const float bb0 = bias[c], bb1 = bias[c + 1];
                v0 += bb0; v1 += bb1; v2 += bb0; v3 += bb1;
                v0 = silu_f(v0); v1 = silu_f(v1);
                v2 = silu_f(v2); v3 = silu_f(v3);
            }
            *(float2*)&C[(size_t)r * ldc + c]       = make_float2(v0, v1);
            *(float2*)&C[(size_t)(r + 8) * ldc + c] = make_float2(v2, v3);
        }
    }
}

// ================== HMMA 3x-bf16 GEMM (NN channel-mix: W_mid, W_res) =========
#define GBM 128
#define GBN 128
#define GBK 16
#define KP  12

template<int EPI, bool BT>
__global__ __launch_bounds__(256, 2)
void tgemm_kernel(const float* __restrict__ A, int lda, size_t sA,
                  const float* __restrict__ B, int ldb, size_t sB,
                  const float* __restrict__ bias,
                  float* __restrict__ C, int ldc, size_t sC,
                  int M, int N, int K)
{
    __shared__ unsigned As_hi[GBM][KP];
    __shared__ unsigned As_lo[GBM][KP];
    __shared__ unsigned Bs_hi[GBN][KP];
    __shared__ unsigned Bs_lo[GBN][KP];

    const int bz = blockIdx.z;
    A += sA * bz; B += sB * bz; C += sC * bz;

    const int m0 = blockIdx.y * GBM;
    const int n0 = blockIdx.x * GBN;
    const int tid = threadIdx.x;
    const int warp = tid >> 5, lane = tid & 31;
    const int wm = warp & 1;
    const int wn = warp >> 1;
    const int g  = lane >> 2;
    const int tg = lane & 3;

    float acc[4][4][4];
    #pragma unroll
    for (int mi = 0; mi < 4; mi++)
        #pragma unroll
        for (int ni = 0; ni < 4; ni++)
            #pragma unroll
            for (int q = 0; q < 4; q++) acc[mi][ni][q] = 0.0f;

    const int a_r  = tid >> 2;
    const int a_c4 = (tid & 3) * 4;
    const int a_cw = a_c4 >> 1;
    const int b_kr = tid >> 5;
    const int b_nc = (tid & 31) * 4;

    float4 pa[2], pb[2];

    #pragma unroll
    for (int i = 0; i < 2; i++) {
        pa[i] = *(const float4*)(A + (size_t)(m0 + a_r + i * 64) * lda + a_c4);
        if (BT)
            pb[i] = *(const float4*)(B + (size_t)(n0 + a_r + i * 64) * ldb + a_c4);
        else
            pb[i] = *(const float4*)(B + (size_t)(b_kr + i * 8) * ldb + n0 + b_nc);
    }

    unsigned short* Bs_hi16 = (unsigned short*)Bs_hi;
    unsigned short* Bs_lo16 = (unsigned short*)Bs_lo;

    int k0 = 0;
    while (true) {
        #pragma unroll
        for (int i = 0; i < 2; i++) {
            uint2 h, l;
            split_pack4(pa[i], h, l);
            *(uint2*)&As_hi[a_r + i * 64][a_cw] = h;
            *(uint2*)&As_lo[a_r + i * 64][a_cw] = l;

            if (BT) {
                split_pack4(pb[i], h, l);
                *(uint2*)&Bs_hi[a_r + i * 64][a_cw] = h;
                *(uint2*)&Bs_lo[a_r + i * 64][a_cw] = l;
            } else {
                const int k = b_kr + i * 8;
                const float* pv = &pb[i].x;
                #pragma unroll
                for (int j = 0; j < 4; j++) {
                    __nv_bfloat16 hh, ll;
                    bf16_split(pv[j], hh, ll);
                    Bs_hi16[(b_nc + j) * (2 * KP) + k] = *(unsigned short*)&hh;
                    Bs_lo16[(b_nc + j) * (2 * KP) + k] = *(unsigned short*)&ll;
                }
            }
        }
        __syncthreads();

        const int kn = k0 + GBK;
        const bool more = kn < K;
        if (more) {
            #pragma unroll
            for (int i = 0; i < 2; i++) {
                pa[i] = *(const float4*)(A + (size_t)(m0 + a_r + i * 64) * lda + kn + a_c4);
                if (BT)
                    pb[i] = *(const float4*)(B + (size_t)(n0 + a_r + i * 64) * ldb + kn + a_c4);
                else
                    pb[i] = *(const float4*)(B + (size_t)(kn + b_kr + i * 8) * ldb + n0 + b_nc);
            }
        }

        {
            unsigned bh[4][2], bl[4][2];
            #pragma unroll
            for (int ni = 0; ni < 4; ni++) {
                const int c = wn * 32 + ni * 8 + g;
                bh[ni][0] = Bs_hi[c][tg];
                bh[ni][1] = Bs_hi[c][tg + 4];
                bl[ni][0] = Bs_lo[c][tg];
                bl[ni][1] = Bs_lo[c][tg + 4];
            }
            #pragma unroll
            for (int mi = 0; mi < 4; mi++) {
                const int r = wm * 64 + mi * 16 + g;
                unsigned ah[4], al[4];
                ah[0] = As_hi[r    ][tg];
                ah[1] = As_hi[r + 8][tg];
                ah[2] = As_hi[r    ][tg + 4];
                ah[3] = As_hi[r + 8][tg + 4];
                al[0] = As_lo[r    ][tg];
                al[1] = As_lo[r + 8][tg];
                al[2] = As_lo[r    ][tg + 4];
                al[3] = As_lo[r + 8][tg + 4];
                #pragma unroll
                for (int ni = 0; ni < 4; ni++) {
                    mma_bf16(acc[mi][ni], ah, bh[ni]);
                    mma_bf16(acc[mi][ni], ah, bl[ni]);
                    mma_bf16(acc[mi][ni], al, bh[ni]);
                }
            }
        }

        if (!more) break;
        __syncthreads();
        k0 = kn;
    }

    #pragma unroll
    for (int mi = 0; mi < 4; mi++) {
        const int r = m0 + wm * 64 + mi * 16 + g;
        #pragma unroll
        for (int ni = 0; ni < 4; ni++) {
            const int c = n0 + wn * 32 + ni * 8 + tg * 2;
            float v0 = acc[mi][ni][0];
            float v1 = acc[mi][ni][1];
            float v2 = acc[mi][ni][2];
            float v3 = acc[mi][ni][3];
            if (EPI == 1) {
                v0 = silu_f(v0); v1 = silu_f(v1);
                v2 = silu_f(v2); v3 = silu_f(v3);
            }
            *(float2*)&C[(size_t)r * ldc + c]       = make_float2(v0, v1);
            *(float2*)&C[(size_t)(r + 8) * ldc + c] = make_float2(v2, v3);
        }
    }
}

// ================== fp32 tiled SGEMM (small shapes: Wx, Wdt) ==================
// EPI: 0 none, 3 softplus(v+bias[n])
#define TBM 64
#define TBN 64
#define TBK 16

template<int EPI, bool BT>
__global__ __launch_bounds__(256)
void gemm_kernel(const float* __restrict__ A, int lda, size_t sA,
                 const float* __restrict__ B, int ldb, size_t sB,
                 const float* __restrict__ bias,
                 float* __restrict__ C, int ldc, size_t sC,
                 int M, int N, int K)
{
    __shared__ float As[TBM][TBK];
    __shared__ float Bs[TBK][TBN];

    const int bz = blockIdx.z;
    A += sA * bz; B += sB * bz; C += sC * bz;

    const int m0 = blockIdx.y * TBM;
    const int n0 = blockIdx.x * TBN;
    const int tid = threadIdx.x;
    const int tx = tid & 15, ty = tid >> 4;

    const int ar  = tid >> 2, ac  = (tid & 3) * 4;
    const int bnr = tid >> 2, bkc = (tid & 3) * 4;
    const int bkr = tid >> 4, bnc = (tid & 15) * 4;

    float acc[4][4];
    #pragma unroll
    for (int i = 0; i < 4; i++)
        #pragma unroll
        for (int j = 0; j < 4; j++) acc[i][j] = 0.0f;

    for (int k0 = 0; k0 < K; k0 += TBK) {
        float4 av = *(const float4*)(A + (size_t)(m0 + ar) * lda + k0 + ac);
        *(float4*)&As[ar][ac] = av;

        if (BT) {
            float4 bv = make_float4(0.f, 0.f, 0.f, 0.f);
            if (n0 + bnr < N)
                bv = *(const float4*)(B + (size_t)(n0 + bnr) * ldb + k0 + bkc);
            Bs[bkc + 0][bnr] = bv.x;
            Bs[bkc + 1][bnr] = bv.y;
            Bs[bkc + 2][bnr] = bv.z;
            Bs[bkc + 3][bnr] = bv.w;
        } else {
            float4 bv = *(const float4*)(B + (size_t)(k0 + bkr) * ldb + n0 + bnc);
            *(float4*)&Bs[bkr][bnc] = bv;
        }
        __syncthreads();

        #pragma unroll
        for (int k = 0; k < TBK; k++) {
            float a0 = As[ty * 4 + 0][k];
            float a1 = As[ty * 4 + 1][k];
            float a2 = As[ty * 4 + 2][k];
            float a3 = As[ty * 4 + 3][k];
            float4 b4 = *(const float4*)&Bs[k][tx * 4];
            acc[0][0] = fmaf(a0, b4.x, acc[0][0]);
            acc[0][1] = fmaf(a0, b4.y, acc[0][1]);
            acc[0][2] = fmaf(a0, b4.z, acc[0][2]);
            acc[0][3] = fmaf(a0, b4.w, acc[0][3]);
            acc[1][0] = fmaf(a1, b4.x, acc[1][0]);
            acc[1][1] = fmaf(a1, b4.y, acc[1][1]);
            acc[1][2] = fmaf(a1, b4.z, acc[1][2]);
            acc[1][3] = fmaf(a1, b4.w, acc[1][3]);
            acc[2][0] = fmaf(a2, b4.x, acc[2][0]);
            acc[2][1] = fmaf(a2, b4.y, acc[2][1]);
            acc[2][2] = fmaf(a2, b4.z, acc[2][2]);
            acc[2][3] = fmaf(a2, b4.w, acc[2][3]);
            acc[3][0] = fmaf(a3, b4.x, acc[3][0]);
            acc[3][1] = fmaf(a3, b4.y, acc[3][1]);
            acc[3][2] = fmaf(a3, b4.z, acc[3][2]);
            acc[3][3] = fmaf(a3, b4.w, acc[3][3]);
        }
        __syncthreads();
    }

    #pragma unroll
    for (int i = 0; i < 4; i++) {
        const int m = m0 + ty * 4 + i;
        #pragma unroll
        for (int j = 0; j < 4; j++) {
            const int n = n0 + tx * 4 + j;
            if (n < N) {
                float v = acc[i][j];
                if (EPI == 3) v = softplus_f(v + bias[n]);
                C[(size_t)m * ldc + n] = v;
            }
        }
    }
}

// ---------------- depthwise causal conv (k=4) + silu --------------------------
__global__ __launch_bounds__(256)
void conv_silu_kernel(const float* __restrict__ xz,
                      const float* __restrict__ convw,
                      const float* __restrict__ convb,
                      float* __restrict__ xi)
{
    const int idx = blockIdx.x * 256 + threadIdx.x;
    const int d = idx & (DMDL - 1);
    const int bl = idx >> 10;
    const int l = bl & (LSEQ - 1);
    const int b = bl >> 8;

    float w0 = convw[d * 4 + 0], w1 = convw[d * 4 + 1];
    float w2 = convw[d * 4 + 2], w3 = convw[d * 4 + 3];

    const size_t base = ((size_t)b * LSEQ) * (2 * DMDL) + d;
    float acc = convb[d];
    if (l >= 3) acc = fmaf(w0, xz[base + (size_t)(l - 3) * (2 * DMDL)], acc);
    if (l >= 2) acc = fmaf(w1, xz[base + (size_t)(l - 2) * (2 * DMDL)], acc);
    if (l >= 1) acc = fmaf(w2, xz[base + (size_t)(l - 1) * (2 * DMDL)], acc);
    acc = fmaf(w3, xz[base + (size_t)l * (2 * DMDL)], acc);

    xi[idx] = silu_f(acc);
}

// ---------------- selective-scan (n=2) fused with skip + gate -----------------
__global__ __launch_bounds__(256)
void scan_kernel(const float* __restrict__ dt,
                 const float* __restrict__ xi,
                 const float* __restrict__ xz,
                 const float* __restrict__ dbl,
                 const float* __restrict__ Alog,
                 const float* __restrict__ Dp,
                 float* __restrict__ y)
{
    const int b = blockIdx.x >> 2;
    const int chunk = blockIdx.x & 3;
    const int d = chunk * 256 + threadIdx.x;

    const float A0 = -expf(Alog[d * 2 + 0]);
    const float A1 = -expf(Alog[d * 2 + 1]);
    const float Dd = Dp[d];

    float h0 = 0.0f, h1 = 0.0f;

    #pragma unroll 4
    for (int l = 0; l < LSEQ; l++) {
        const int bl = b * LSEQ + l;
        const size_t idx = (size_t)bl * DMDL + d;
        const float dtv = dt[idx];
        const float xiv = xi[idx];
        const float zv  = xz[(size_t)bl * (2 * DMDL) + DMDL + d];
        const float* bc = dbl + (size_t)bl * DTOT + DTR;
        const float B0 = bc[0], B1 = bc[1], C0 = bc[2], C1 = bc[3];

        const float dBx = dtv * xiv;
        h0 = fmaf(expf(dtv * A0), h0, dBx * B0);
        h1 = fmaf(expf(dtv * A1), h1, dBx * B1);

        float yv = fmaf(h0, C0, h1 * C1);
        yv = fmaf(Dd, xiv, yv);
        y[idx] = yv * silu_f(zv);
    }
}

// ---------------- LayerNorm (in-place) ----------------------------------------
__global__ __launch_bounds__(256)
void ln_kernel(float* __restrict__ x,
               const float* __restrict__ g,
               const float* __restrict__ b)
{
    __shared__ float red[256];
    const int tid = threadIdx.x;
    float* p = x + (size_t)blockIdx.x * DMDL;

    float v[4];
    float s = 0.0f;
    #pragma unroll
    for (int i = 0; i < 4; i++) { v[i] = p[tid + i * 256]; s += v[i]; }

    red[tid] = s; __syncthreads();
    for (int o = 128; o > 0; o >>= 1) {
        if (tid < o) red[tid] += red[tid + o];
        __syncthreads();
    }
    const float mean = red[0] * (1.0f / DMDL);
    __syncthreads();

    float sq = 0.0f;
    #pragma unroll
    for (int i = 0; i < 4; i++) { float dd = v[i] - mean; sq += dd * dd; }
    red[tid] = sq; __syncthreads();
    for (int o = 128; o > 0; o >>= 1) {
        if (tid < o) red[tid] += red[tid + o];
        __syncthreads();
    }
    const float rstd = rsqrtf(red[0] * (1.0f / DMDL) + 1e-5f);

    #pragma unroll
    for (int i = 0; i < 4; i++) {
        const int c = tid + i * 256;
        p[c] = (v[i] - mean) * rstd * g[c] + b[c];
    }
}

// ---------------- final fused add + silu --------------------------------------
__global__ __launch_bounds__(256)
void final_kernel(const float* __restrict__ s,
                  const float* __restrict__ r,
                  float* __restrict__ out)
{
    const int i = blockIdx.x * 256 + threadIdx.x;
    out[i] = silu_f(s[i] + r[i]);
}

// ---------------- host orchestration ------------------------------------------
struct Scratch {
    float *xz, *xi, *dbl, *dt, *y, *s, *t, *r, *r2;
    uint32_t *Ah, *Al, *Bh, *Bl;
};

static void do_split(const float* src, uint32_t* hi, uint32_t* lo, int nElem) {
    split_kernel<<<nElem / 2048, 256>>>((const float4*)src, (uint4*)hi, (uint4*)lo);
}

static void run_mamba(const float* X,
                      const float* Win, const float* convw, const float* convb,
                      const float* Wx, const float* Wdt, const float* bdt,
                      const float* Alog, const float* Dp, const float* Wout,
                      const Scratch& sc, float* out, bool x_presplit)
{
    dim3 blk(256);
    // xz = X @ Win^T   (4096 x 2048, K=1024)
    if (!x_presplit) do_split(X, sc.Ah, sc.Al, MROWS * DMDL);
    do_split(Win, sc.Bh, sc.Bl, 2 * DMDL * DMDL);
    bgemm_kernel<0><<<dim3((2 * DMDL) / 128, MROWS / 128), blk>>>(
        sc.Ah, sc.Al, sc.Bh, sc.Bl, nullptr, sc.xz, 2 * DMDL, MROWS, 2 * DMDL, DMDL);
    // xi = silu(conv(xz[:,:,:di]))
    conv_silu_kernel<<<(MROWS * DMDL) / 256, blk>>>(sc.xz, convw, convb, sc.xi);
    // dbl = xi @ Wx^T  (4096 x 68, K=1024)  — fp32 (tiny N)
    gemm_kernel<0, true><<<dim3((DTOT + TBN - 1) / TBN, MROWS / TBM), blk>>>(
        sc.xi, DMDL, 0, Wx, DMDL, 0, nullptr, sc.dbl, DTOT, 0, MROWS, DTOT, DMDL);
    // dt = softplus(dbl[:,:64] @ Wdt^T + bdt)  — fp32 (feeds exp)
    gemm_kernel<3, true><<<dim3(DMDL / TBN, MROWS / TBM), blk>>>(
        sc.dbl, DTOT, 0, Wdt, DTR, 0, bdt, sc.dt, DMDL, 0, MROWS, DMDL, DTR);
    // selective scan + skip + gate
    scan_kernel<<<BATCH * (DMDL / 256), blk>>>(sc.dt, sc.xi, sc.xz, sc.dbl, Alog, Dp, sc.y);
    // out = y @ Wout^T  (4096 x 1024, K=1024)
    do_split(sc.y, sc.Ah, sc.Al, MROWS * DMDL);
    do_split(Wout, sc.Bh, sc.Bl, DMDL * DMDL);
    bgemm_kernel<0><<<dim3(DMDL / 128, MROWS / 128), blk>>>(
        sc.Ah, sc.Al, sc.Bh, sc.Bl, nullptr, out, DMDL, MROWS, DMDL, DMDL);
}

extern "C" void kernel_launch(void* const* d_in, const int* in_sizes, int n_in,
                              void* d_out, int out_size)
{
    (void)in_sizes; (void)n_in; (void)out_size;

    const float* x        = (const float*)d_in[0];
    const float* m1_Win   = (const float*)d_in[1];
    const float* m1_convw = (const float*)d_in[2];
    const float* m1_convb = (const float*)d_in[3];
    const float* m1_Wx    = (const float*)d_in[4];
    const float* m1_Wdt   = (const float*)d_in[5];
    const float* m1_bdt   = (const float*)d_in[6];
    const float* m1_Alog  = (const float*)d_in[7];
    const float* m1_D     = (const float*)d_in[8];
    const float* m1_Wout  = (const float*)d_in[9];
    const float* m2_Win   = (const float*)d_in[10];
    const float* m2_convw = (const float*)d_in[11];
    const float* m2_convb = (const float*)d_in[12];
    const float* m2_Wx    = (const float*)d_in[13];
    const float* m2_Wdt   = (const float*)d_in[14];
    const float* m2_bdt   = (const float*)d_in[15];
    const float* m2_Alog  = (const float*)d_in[16];
    const float* m2_D     = (const float*)d_in[17];
    const float* m2_Wout  = (const float*)d_in[18];
    const float* ln1_g    = (const float*)d_in[19];
    const float* ln1_b    = (const float*)d_in[20];
    const float* ln2_g    = (const float*)d_in[21];
    const float* ln2_b    = (const float*)d_in[22];
    const float* W_mid    = (const float*)d_in[23];
    const float* W_spa    = (const float*)d_in[24];
    const float* b_spa    = (const float*)d_in[25];
    const float* W_res    = (const float*)d_in[26];
    float* out = (float*)d_out;

    Scratch sc;
    void* p;
    cudaGetSymbolAddress(&p, g_xz);  sc.xz  = (float*)p;
    cudaGetSymbolAddress(&p, g_xi);  sc.xi  = (float*)p;
    cudaGetSymbolAddress(&p, g_dbl); sc.dbl = (float*)p;
    cudaGetSymbolAddress(&p, g_dt);  sc.dt  = (float*)p;
    cudaGetSymbolAddress(&p, g_y);   sc.y   = (float*)p;
    cudaGetSymbolAddress(&p, g_s);   sc.s   = (float*)p;
    cudaGetSymbolAddress(&p, g_t);   sc.t   = (float*)p;
    cudaGetSymbolAddress(&p, g_r);   sc.r   = (float*)p;
    cudaGetSymbolAddress(&p, g_r2);  sc.r2  = (float*)p;
    cudaGetSymbolAddress(&p, g_Ah);  sc.Ah  = (uint32_t*)p;
    cudaGetSymbolAddress(&p, g_Al);  sc.Al  = (uint32_t*)p;
    cudaGetSymbolAddress(&p, g_Bh);  sc.Bh  = (uint32_t*)p;
    cudaGetSymbolAddress(&p, g_Bl);  sc.Bl  = (uint32_t*)p;

    dim3 blk(256);
    const size_t bstride = (size_t)LSEQ * DMDL;

    // ---- residual path first (reuses the x split for stage-1 Win)
    do_split(x, sc.Ah, sc.Al, MROWS * DMDL);
    do_split(W_spa, sc.Bh, sc.Bl, DMDL * DMDL);
    bgemm_kernel<2><<<dim3(DMDL / 128, MROWS / 128), blk>>>(
        sc.Ah, sc.Al, sc.Bh, sc.Bl, b_spa, sc.r, DMDL, MROWS, DMDL, DMDL);
    // r2 = silu(channel-mix with W_res)  (batched NN, HMMA)
    tgemm_kernel<1, false><<<dim3(DMDL / GBN, LSEQ / GBM, BATCH), blk>>>(
        W_res, LSEQ, 0, sc.r, DMDL, bstride, nullptr, sc.r2, DMDL, bstride,
        LSEQ, DMDL, LSEQ);

    // ---- stage 1: mamba1 -> s   (x already split in Ah/Al)
    run_mamba(x, m1_Win, m1_convw, m1_convb, m1_Wx, m1_Wdt, m1_bdt,
              m1_Alog, m1_D, m1_Wout, sc, sc.s, /*x_presplit=*/true);
    ln_kernel<<<MROWS, blk>>>(sc.s, ln1_g, ln1_b);
    // t[b,o,sp] = silu(sum_c W_mid[o,c] * s[b,c,sp])  (batched NN, HMMA)
    tgemm_kernel<1, false><<<dim3(DMDL / GBN, LSEQ / GBM, BATCH), blk>>>(
        W_mid, LSEQ, 0, sc.s, DMDL, bstride, nullptr, sc.t, DMDL, bstride,
        LSEQ, DMDL, LSEQ);

    // ---- stage 2: mamba2 -> s
    run_mamba(sc.t, m2_Win, m2_convw, m2_convb, m2_Wx, m2_Wdt, m2_bdt,
              m2_Alog, m2_D, m2_Wout, sc, sc.s, /*x_presplit=*/false);
    ln_kernel<<<MROWS, blk>>>(sc.s, ln2_g, ln2_b);

    // ---- out = silu(s + r2)
    final_kernel<<<(MROWS * DMDL) / 256, blk>>>(sc.s, sc.r2, out);
}

// round 13
// speedup vs baseline: 1.0201x; 1.0201x over previous
#include <cuda_runtime.h>
#include <cuda_bf16.h>
#include <math.h>
#include <stdint.h>

// Problem constants
#define BATCH 16
#define LSEQ  256
#define DMDL  1024           // dm == di
#define DTOT  68             // dtr + 2*n
#define DTR   64
#define MROWS (BATCH*LSEQ)   // 4096

// ---------------- scratch (device globals; no allocations allowed) ----------
__device__ float g_xz [BATCH*LSEQ*2*DMDL];
__device__ float g_xi [BATCH*LSEQ*DMDL];
__device__ float g_dbl[BATCH*LSEQ*DTOT];
__device__ float g_dt [BATCH*LSEQ*DMDL];
__device__ float g_y  [BATCH*LSEQ*DMDL];
__device__ float g_s  [BATCH*LSEQ*DMDL];
__device__ float g_t  [BATCH*LSEQ*DMDL];
__device__ float g_r  [BATCH*LSEQ*DMDL];
__device__ float g_r2 [BATCH*LSEQ*DMDL];
// packed bf16 hi/lo operand buffers for the big GEMMs
__device__ uint32_t g_Ah[MROWS*(DMDL/2)];      // activations: 4096 x 512 u32
__device__ uint32_t g_Al[MROWS*(DMDL/2)];
__device__ uint32_t g_Bh[(2*DMDL)*(DMDL/2)];   // weights: 2048 x 512 u32
__device__ uint32_t g_Bl[(2*DMDL)*(DMDL/2)];

// ---------------- helpers ----------------------------------------------------
__device__ __forceinline__ float silu_f(float v) {
    return v / (1.0f + expf(-v));
}
__device__ __forceinline__ float softplus_f(float v) {
    return fmaxf(v, 0.0f) + log1pf(expf(-fabsf(v)));
}
__device__ __forceinline__ unsigned pack_bf2(__nv_bfloat16 a, __nv_bfloat16 b) {
    __nv_bfloat162 t(a, b);
    return *reinterpret_cast<unsigned*>(&t);
}
__device__ __forceinline__ void bf16_split(float x, __nv_bfloat16& h, __nv_bfloat16& l) {
    h = __float2bfloat16_rn(x);
    l = __float2bfloat16_rn(x - __bfloat162float(h));
}
__device__ __forceinline__ void split_pack4(float4 v, uint2& h, uint2& l) {
    __nv_bfloat16 hx, hy, hz, hw, lx, ly, lz, lw;
    bf16_split(v.x, hx, lx);
    bf16_split(v.y, hy, ly);
    bf16_split(v.z, hz, lz);
    bf16_split(v.w, hw, lw);
    h.x = pack_bf2(hx, hy); h.y = pack_bf2(hz, hw);
    l.x = pack_bf2(lx, ly); l.y = pack_bf2(lz, lw);
}
__device__ __forceinline__ void mma_bf16(float* c, const unsigned* a, const unsigned* b) {
    asm volatile(
        "mma.sync.aligned.m16n8k16.row.col.f32.bf16.bf16.f32 "
        "{%0,%1,%2,%3},{%4,%5,%6,%7},{%8,%9},{%0,%1,%2,%3};\n"
        : "+f"(c[0]), "+f"(c[1]), "+f"(c[2]), "+f"(c[3])
        : "r"(a[0]), "r"(a[1]), "r"(a[2]), "r"(a[3]), "r"(b[0]), "r"(b[1]));
}
__device__ __forceinline__ uint32_t smem_u32(const void* p) {
    uint32_t a;
    asm("{ .reg .u64 t; cvta.to.shared.u64 t, %1; cvt.u32.u64 %0, t; }" : "=r"(a) : "l"(p));
    return a;
}
__device__ __forceinline__ void ldsm_x4(unsigned* r, uint32_t addr) {
    asm volatile("ldmatrix.sync.aligned.m8n8.x4.shared.b16 {%0,%1,%2,%3}, [%4];"
                 : "=r"(r[0]), "=r"(r[1]), "=r"(r[2]), "=r"(r[3]) : "r"(addr));
}
__device__ __forceinline__ void cp_async16(uint32_t sa, const void* gp) {
    asm volatile("cp.async.cg.shared.global [%0], [%1], 16;" :: "r"(sa), "l"(gp));
}
__device__ __forceinline__ void cp_commit() {
    asm volatile("cp.async.commit_group;" ::: "memory");
}
template<int N>
__device__ __forceinline__ void cp_wait() {
    asm volatile("cp.async.wait_group %0;" :: "n"(N) : "memory");
}

// ================== pre-split: fp32 -> packed bf16 hi/lo ======================
__global__ __launch_bounds__(256)
void split_kernel(const float4* __restrict__ in,
                  uint4* __restrict__ hi, uint4* __restrict__ lo)
{
    const size_t i = (size_t)blockIdx.x * 256 + threadIdx.x;
    float4 a = in[2 * i], b = in[2 * i + 1];
    uint2 ha, la, hb, lb;
    split_pack4(a, ha, la);
    split_pack4(b, hb, lb);
    hi[i] = make_uint4(ha.x, ha.y, hb.x, hb.y);
    lo[i] = make_uint4(la.x, la.y, lb.x, lb.y);
}

// ================== 3x-bf16 LDSM GEMM v2: cp.async, BK=32, 2 stages ==========
// C[m,n] = epi( sum_k A[m,k]*B[n,k] ); operands pre-split hi/lo packed u32.
// M%128==0, N%128==0, K%32==0.  EPI: 0 none, 2 silu(v+bias[n])
// smem (dynamic): 2 stages x 4 tiles(Ah,Al,Bh,Bl) x [128 rows x 20 u32]
#define BG_ROW    20                       // u32 row stride (conflict-free LDSM)
#define BG_TILE_B (128*BG_ROW*4)           // 10240 bytes
#define BG_STG_B  (4*BG_TILE_B)            // 40960 bytes per stage
#define BG_SMEM   (2*BG_STG_B)             // 81920 bytes

template<int EPI>
__global__ __launch_bounds__(256, 2)
void bgemm_kernel(const uint32_t* __restrict__ Ah, const uint32_t* __restrict__ Al,
                  const uint32_t* __restrict__ Bh, const uint32_t* __restrict__ Bl,
                  const float* __restrict__ bias,
                  float* __restrict__ C, int ldc, int M, int N, int K)
{
    extern __shared__ char smem[];
    const uint32_t sb = smem_u32(smem);

    const int ld2 = K >> 1;                 // u32 per row
    const int m0 = blockIdx.y * 128;
    const int n0 = blockIdx.x * 128;
    const int tid = threadIdx.x;
    const int warp = tid >> 5, lane = tid & 31;
    const int wm = warp & 1;                // 2 warps along M
    const int wn = warp >> 1;               // 4 warps along N
    const int g  = lane >> 2;
    const int tg = lane & 3;

    float acc[4][4][4];
    #pragma unroll
    for (int mi = 0; mi < 4; mi++)
        #pragma unroll
        for (int ni = 0; ni < 4; ni++)
            #pragma unroll
            for (int q = 0; q < 4; q++) acc[mi][ni][q] = 0.0f;

    // loader map: thread -> (row 0..127, 8-u32 half of the 16-u32 row)
    const int lrow = tid >> 1;
    const int lc   = (tid & 1) * 8;
    const size_t gA = (size_t)(m0 + lrow) * ld2 + lc;
    const size_t gB = (size_t)(n0 + lrow) * ld2 + lc;
    const uint32_t sLoad = sb + (uint32_t)((lrow * BG_ROW + lc) * 4);

    // ldmatrix lane offsets (within a tile)
    const uint32_t oA = (uint32_t)(((wm * 64 + (lane & 15)) * BG_ROW + (lane >> 4) * 4) * 4);
    const uint32_t oB = (uint32_t)(((wn * 32 + ((lane >> 4) * 8) + (lane & 7)) * BG_ROW
                                    + ((lane >> 3) & 1) * 4) * 4);

    const int nIter = K >> 5;               // K/32

    // issue one stage of cp.async (16 u32 per row = 2 chunks per thread per tile)
    auto issue = [&](int it, int stage) {
        const size_t k2 = (size_t)(it << 4);    // it*32/2 u32
        const uint32_t sa = sLoad + stage * BG_STG_B;
        cp_async16(sa + 0 * BG_TILE_B,      Ah + gA + k2);
        cp_async16(sa + 0 * BG_TILE_B + 16, Ah + gA + k2 + 4);
        cp_async16(sa + 1 * BG_TILE_B,      Al + gA + k2);
        cp_async16(sa + 1 * BG_TILE_B + 16, Al + gA + k2 + 4);
        cp_async16(sa + 2 * BG_TILE_B,      Bh + gB + k2);
        cp_async16(sa + 2 * BG_TILE_B + 16, Bh + gB + k2 + 4);
        cp_async16(sa + 3 * BG_TILE_B,      Bl + gB + k2);
        cp_async16(sa + 3 * BG_TILE_B + 16, Bl + gB + k2 + 4);
        cp_commit();
    };

    issue(0, 0);

    for (int it = 0; it < nIter; it++) {
        const int stage = it & 1;
        const bool more = (it + 1) < nIter;
        if (more) issue(it + 1, stage ^ 1);

        if (more) cp_wait<1>(); else cp_wait<0>();
        __syncthreads();

        const uint32_t so = sb + stage * BG_STG_B;
        const uint32_t aAh = so + oA;
        const uint32_t aAl = aAh + BG_TILE_B;
        const uint32_t aBh = so + 2 * BG_TILE_B + oB;
        const uint32_t aBl = aBh + BG_TILE_B;

        #pragma unroll
        for (int h = 0; h < 2; h++) {           // two k16 chunks in BK=32
            const uint32_t ko = h * 32;         // +8 u32
            unsigned qh[2][4], ql[2][4];
            #pragma unroll
            for (int p = 0; p < 2; p++) {
                ldsm_x4(qh[p], aBh + p * 16 * (BG_ROW * 4) + ko);
                ldsm_x4(ql[p], aBl + p * 16 * (BG_ROW * 4) + ko);
            }
            #pragma unroll
            for (int mi = 0; mi < 4; mi++) {
                unsigned ah[4], al[4];
                ldsm_x4(ah, aAh + mi * 16 * (BG_ROW * 4) + ko);
                ldsm_x4(al, aAl + mi * 16 * (BG_ROW * 4) + ko);
                #pragma unroll
                for (int ni = 0; ni < 4; ni++) {
                    const int p = ni >> 1, s = (ni & 1) * 2;
                    mma_bf16(acc[mi][ni], ah, &qh[p][s]);   // hi*hi
                    mma_bf16(acc[mi][ni], ah, &ql[p][s]);   // hi*lo
                    mma_bf16(acc[mi][ni], al, &qh[p][s]);   // lo*hi
                }
            }
        }
        __syncthreads();
    }

    // epilogue
    #pragma unroll
    for (int mi = 0; mi < 4; mi++) {
        const int r = m0 + wm * 64 + mi * 16 + g;
        #pragma unroll
        for (int ni = 0; ni < 4; ni++) {
            const int c = n0 + wn * 32 + ni * 8 + tg * 2;
            float v0 = acc[mi][ni][0];
            float v1 = acc[mi][ni][1];
            float v2 = acc[mi][ni][2];
            float v3 = acc[mi][ni][3];
            if (EPI == 2) {
                const float bb0 = bias[c], bb1 = bias[c + 1];
                v0 += bb0; v1 += bb1; v2 += bb0; v3 += bb1;
                v0 = silu_f(v0); v1 = silu_f(v1);
                v2 = silu_f(v2); v3 = silu_f(v3);
            }
            *(float2*)&C[(size_t)r * ldc + c]       = make_float2(v0, v1);
            *(float2*)&C[(size_t)(r + 8) * ldc + c] = make_float2(v2, v3);
        }
    }
}

// ================== HMMA 3x-bf16 GEMM (NN channel-mix: W_mid, W_res) =========
// KP=13 (odd stride kills u16 scatter-store conflicts). NOTE: odd row stride
// means rows are only 4B-aligned -> ALL smem stores here are scalar u32/u16.
#define GBM 128
#define GBN 128
#define GBK 16
#define KP  13

template<int EPI, bool BT>
__global__ __launch_bounds__(256, 2)
void tgemm_kernel(const float* __restrict__ A, int lda, size_t sA,
                  const float* __restrict__ B, int ldb, size_t sB,
                  const float* __restrict__ bias,
                  float* __restrict__ C, int ldc, size_t sC,
                  int M, int N, int K)
{
    __shared__ unsigned As_hi[GBM][KP];
    __shared__ unsigned As_lo[GBM][KP];
    __shared__ unsigned Bs_hi[GBN][KP];
    __shared__ unsigned Bs_lo[GBN][KP];

    const int bz = blockIdx.z;
    A += sA * bz; B += sB * bz; C += sC * bz;

    const int m0 = blockIdx.y * GBM;
    const int n0 = blockIdx.x * GBN;
    const int tid = threadIdx.x;
    const int warp = tid >> 5, lane = tid & 31;
    const int wm = warp & 1;
    const int wn = warp >> 1;
    const int g  = lane >> 2;
    const int tg = lane & 3;

    float acc[4][4][4];
    #pragma unroll
    for (int mi = 0; mi < 4; mi++)
        #pragma unroll
        for (int ni = 0; ni < 4; ni++)
            #pragma unroll
            for (int q = 0; q < 4; q++) acc[mi][ni][q] = 0.0f;

    const int a_r  = tid >> 2;
    const int a_c4 = (tid & 3) * 4;
    const int a_cw = a_c4 >> 1;
    const int b_kr = tid >> 5;
    const int b_nc = (tid & 31) * 4;

    float4 pa[2], pb[2];

    #pragma unroll
    for (int i = 0; i < 2; i++) {
        pa[i] = *(const float4*)(A + (size_t)(m0 + a_r + i * 64) * lda + a_c4);
        if (BT)
            pb[i] = *(const float4*)(B + (size_t)(n0 + a_r + i * 64) * ldb + a_c4);
        else
            pb[i] = *(const float4*)(B + (size_t)(b_kr + i * 8) * ldb + n0 + b_nc);
    }

    unsigned short* Bs_hi16 = (unsigned short*)Bs_hi;
    unsigned short* Bs_lo16 = (unsigned short*)Bs_lo;

    int k0 = 0;
    while (true) {
        #pragma unroll
        for (int i = 0; i < 2; i++) {
            uint2 h, l;
            split_pack4(pa[i], h, l);
            // scalar u32 stores (odd KP -> rows only 4B-aligned)
            As_hi[a_r + i * 64][a_cw]     = h.x;
            As_hi[a_r + i * 64][a_cw + 1] = h.y;
            As_lo[a_r + i * 64][a_cw]     = l.x;
            As_lo[a_r + i * 64][a_cw + 1] = l.y;

            if (BT) {
                split_pack4(pb[i], h, l);
                Bs_hi[a_r + i * 64][a_cw]     = h.x;
                Bs_hi[a_r + i * 64][a_cw + 1] = h.y;
                Bs_lo[a_r + i * 64][a_cw]     = l.x;
                Bs_lo[a_r + i * 64][a_cw + 1] = l.y;
            } else {
                const int k = b_kr + i * 8;
                const float* pv = &pb[i].x;
                #pragma unroll
                for (int j = 0; j < 4; j++) {
                    __nv_bfloat16 hh, ll;
                    bf16_split(pv[j], hh, ll);
                    Bs_hi16[(b_nc + j) * (2 * KP) + k] = *(unsigned short*)&hh;
                    Bs_lo16[(b_nc + j) * (2 * KP) + k] = *(unsigned short*)&ll;
                }
            }
        }
        __syncthreads();

        const int kn = k0 + GBK;
        const bool more = kn < K;
        if (more) {
            #pragma unroll
            for (int i = 0; i < 2; i++) {
                pa[i] = *(const float4*)(A + (size_t)(m0 + a_r + i * 64) * lda + kn + a_c4);
                if (BT)
                    pb[i] = *(const float4*)(B + (size_t)(n0 + a_r + i * 64) * ldb + kn + a_c4);
                else
                    pb[i] = *(const float4*)(B + (size_t)(kn + b_kr + i * 8) * ldb + n0 + b_nc);
            }
        }

        {
            unsigned bh[4][2], bl[4][2];
            #pragma unroll
            for (int ni = 0; ni < 4; ni++) {
                const int c = wn * 32 + ni * 8 + g;
                bh[ni][0] = Bs_hi[c][tg];
                bh[ni][1] = Bs_hi[c][tg + 4];
                bl[ni][0] = Bs_lo[c][tg];
                bl[ni][1] = Bs_lo[c][tg + 4];
            }
            #pragma unroll
            for (int mi = 0; mi < 4; mi++) {
                const int r = wm * 64 + mi * 16 + g;
                unsigned ah[4], al[4];
                ah[0] = As_hi[r    ][tg];
                ah[1] = As_hi[r + 8][tg];
                ah[2] = As_hi[r    ][tg + 4];
                ah[3] = As_hi[r + 8][tg + 4];
                al[0] = As_lo[r    ][tg];
                al[1] = As_lo[r + 8][tg];
                al[2] = As_lo[r    ][tg + 4];
                al[3] = As_lo[r + 8][tg + 4];
                #pragma unroll
                for (int ni = 0; ni < 4; ni++) {
                    mma_bf16(acc[mi][ni], ah, bh[ni]);
                    mma_bf16(acc[mi][ni], ah, bl[ni]);
                    mma_bf16(acc[mi][ni], al, bh[ni]);
                }
            }
        }

        if (!more) break;
        __syncthreads();
        k0 = kn;
    }

    #pragma unroll
    for (int mi = 0; mi < 4; mi++) {
        const int r = m0 + wm * 64 + mi * 16 + g;
        #pragma unroll
        for (int ni = 0; ni < 4; ni++) {
            const int c = n0 + wn * 32 + ni * 8 + tg * 2;
            float v0 = acc[mi][ni][0];
            float v1 = acc[mi][ni][1];
            float v2 = acc[mi][ni][2];
            float v3 = acc[mi][ni][3];
            if (EPI == 1) {
                v0 = silu_f(v0); v1 = silu_f(v1);
                v2 = silu_f(v2); v3 = silu_f(v3);
            }
            *(float2*)&C[(size_t)r * ldc + c]       = make_float2(v0, v1);
            *(float2*)&C[(size_t)(r + 8) * ldc + c] = make_float2(v2, v3);
        }
    }
}

// ================== fp32 tiled SGEMM (small shapes: Wx, Wdt) ==================
#define TBM 64
#define TBN 64
#define TBK 16

template<int EPI, bool BT>
__global__ __launch_bounds__(256)
void gemm_kernel(const float* __restrict__ A, int lda, size_t sA,
                 const float* __restrict__ B, int ldb, size_t sB,
                 const float* __restrict__ bias,
                 float* __restrict__ C, int ldc, size_t sC,
                 int M, int N, int K)
{
    __shared__ float As[TBM][TBK];
    __shared__ float Bs[TBK][TBN];

    const int bz = blockIdx.z;
    A += sA * bz; B += sB * bz; C += sC * bz;

    const int m0 = blockIdx.y * TBM;
    const int n0 = blockIdx.x * TBN;
    const int tid = threadIdx.x;
    const int tx = tid & 15, ty = tid >> 4;

    const int ar  = tid >> 2, ac  = (tid & 3) * 4;
    const int bnr = tid >> 2, bkc = (tid & 3) * 4;
    const int bkr = tid >> 4, bnc = (tid & 15) * 4;

    float acc[4][4];
    #pragma unroll
    for (int i = 0; i < 4; i++)
        #pragma unroll
        for (int j = 0; j < 4; j++) acc[i][j] = 0.0f;

    for (int k0 = 0; k0 < K; k0 += TBK) {
        float4 av = *(const float4*)(A + (size_t)(m0 + ar) * lda + k0 + ac);
        *(float4*)&As[ar][ac] = av;

        if (BT) {
            float4 bv = make_float4(0.f, 0.f, 0.f, 0.f);
            if (n0 + bnr < N)
                bv = *(const float4*)(B + (size_t)(n0 + bnr) * ldb + k0 + bkc);
            Bs[bkc + 0][bnr] = bv.x;
            Bs[bkc + 1][bnr] = bv.y;
            Bs[bkc + 2][bnr] = bv.z;
            Bs[bkc + 3][bnr] = bv.w;
        } else {
            float4 bv = *(const float4*)(B + (size_t)(k0 + bkr) * ldb + n0 + bnc);
            *(float4*)&Bs[bkr][bnc] = bv;
        }
        __syncthreads();

        #pragma unroll
        for (int k = 0; k < TBK; k++) {
            float a0 = As[ty * 4 + 0][k];
            float a1 = As[ty * 4 + 1][k];
            float a2 = As[ty * 4 + 2][k];
            float a3 = As[ty * 4 + 3][k];
            float4 b4 = *(const float4*)&Bs[k][tx * 4];
            acc[0][0] = fmaf(a0, b4.x, acc[0][0]);
            acc[0][1] = fmaf(a0, b4.y, acc[0][1]);
            acc[0][2] = fmaf(a0, b4.z, acc[0][2]);
            acc[0][3] = fmaf(a0, b4.w, acc[0][3]);
            acc[1][0] = fmaf(a1, b4.x, acc[1][0]);
            acc[1][1] = fmaf(a1, b4.y, acc[1][1]);
            acc[1][2] = fmaf(a1, b4.z, acc[1][2]);
            acc[1][3] = fmaf(a1, b4.w, acc[1][3]);
            acc[2][0] = fmaf(a2, b4.x, acc[2][0]);
            acc[2][1] = fmaf(a2, b4.y, acc[2][1]);
            acc[2][2] = fmaf(a2, b4.z, acc[2][2]);
            acc[2][3] = fmaf(a2, b4.w, acc[2][3]);
            acc[3][0] = fmaf(a3, b4.x, acc[3][0]);
            acc[3][1] = fmaf(a3, b4.y, acc[3][1]);
            acc[3][2] = fmaf(a3, b4.z, acc[3][2]);
            acc[3][3] = fmaf(a3, b4.w, acc[3][3]);
        }
        __syncthreads();
    }

    #pragma unroll
    for (int i = 0; i < 4; i++) {
        const int m = m0 + ty * 4 + i;
        #pragma unroll
        for (int j = 0; j < 4; j++) {
            const int n = n0 + tx * 4 + j;
            if (n < N) {
                float v = acc[i][j];
                if (EPI == 3) v = softplus_f(v + bias[n]);
                C[(size_t)m * ldc + n] = v;
            }
        }
    }
}

// ---------------- depthwise causal conv (k=4) + silu --------------------------
__global__ __launch_bounds__(256)
void conv_silu_kernel(const float* __restrict__ xz,
                      const float* __restrict__ convw,
                      const float* __restrict__ convb,
                      float* __restrict__ xi)
{
    const int idx = blockIdx.x * 256 + threadIdx.x;
    const int d = idx & (DMDL - 1);
    const int bl = idx >> 10;
    const int l = bl & (LSEQ - 1);
    const int b = bl >> 8;

    float w0 = convw[d * 4 + 0], w1 = convw[d * 4 + 1];
    float w2 = convw[d * 4 + 2], w3 = convw[d * 4 + 3];

    const size_t base = ((size_t)b * LSEQ) * (2 * DMDL) + d;
    float acc = convb[d];
    if (l >= 3) acc = fmaf(w0, xz[base + (size_t)(l - 3) * (2 * DMDL)], acc);
    if (l >= 2) acc = fmaf(w1, xz[base + (size_t)(l - 2) * (2 * DMDL)], acc);
    if (l >= 1) acc = fmaf(w2, xz[base + (size_t)(l - 1) * (2 * DMDL)], acc);
    acc = fmaf(w3, xz[base + (size_t)l * (2 * DMDL)], acc);

    xi[idx] = silu_f(acc);
}

// ---------------- selective-scan (n=2) fused with skip + gate -----------------
__global__ __launch_bounds__(256)
void scan_kernel(const float* __restrict__ dt,
                 const float* __restrict__ xi,
                 const float* __restrict__ xz,
                 const float* __restrict__ dbl,
                 const float* __restrict__ Alog,
                 const float* __restrict__ Dp,
                 float* __restrict__ y)
{
    const int b = blockIdx.x >> 2;
    const int chunk = blockIdx.x & 3;
    const int d = chunk * 256 + threadIdx.x;

    const float A0 = -expf(Alog[d * 2 + 0]);
    const float A1 = -expf(Alog[d * 2 + 1]);
    const float Dd = Dp[d];

    float h0 = 0.0f, h1 = 0.0f;

    #pragma unroll 4
    for (int l = 0; l < LSEQ; l++) {
        const int bl = b * LSEQ + l;
        const size_t idx = (size_t)bl * DMDL + d;
        const float dtv = dt[idx];
        const float xiv = xi[idx];
        const float zv  = xz[(size_t)bl * (2 * DMDL) + DMDL + d];
        const float* bc = dbl + (size_t)bl * DTOT + DTR;
        const float B0 = bc[0], B1 = bc[1], C0 = bc[2], C1 = bc[3];

        const float dBx = dtv * xiv;
        h0 = fmaf(expf(dtv * A0), h0, dBx * B0);
        h1 = fmaf(expf(dtv * A1), h1, dBx * B1);

        float yv = fmaf(h0, C0, h1 * C1);
        yv = fmaf(Dd, xiv, yv);
        y[idx] = yv * silu_f(zv);
    }
}

// ---------------- LayerNorm (in-place) ----------------------------------------
__global__ __launch_bounds__(256)
void ln_kernel(float* __restrict__ x,
               const float* __restrict__ g,
               const float* __restrict__ b)
{
    __shared__ float red[256];
    const int tid = threadIdx.x;
    float* p = x + (size_t)blockIdx.x * DMDL;

    float v[4];
    float s = 0.0f;
    #pragma unroll
    for (int i = 0; i < 4; i++) { v[i] = p[tid + i * 256]; s += v[i]; }

    red[tid] = s; __syncthreads();
    for (int o = 128; o > 0; o >>= 1) {
        if (tid < o) red[tid] += red[tid + o];
        __syncthreads();
    }
    const float mean = red[0] * (1.0f / DMDL);
    __syncthreads();

    float sq = 0.0f;
    #pragma unroll
    for (int i = 0; i < 4; i++) { float dd = v[i] - mean; sq += dd * dd; }
    red[tid] = sq; __syncthreads();
    for (int o = 128; o > 0; o >>= 1) {
        if (tid < o) red[tid] += red[tid + o];
        __syncthreads();
    }
    const float rstd = rsqrtf(red[0] * (1.0f / DMDL) + 1e-5f);

    #pragma unroll
    for (int i = 0; i < 4; i++) {
        const int c = tid + i * 256;
        p[c] = (v[i] - mean) * rstd * g[c] + b[c];
    }
}

// ---------------- final fused add + silu --------------------------------------
__global__ __launch_bounds__(256)
void final_kernel(const float* __restrict__ s,
                  const float* __restrict__ r,
                  float* __restrict__ out)
{
    const int i = blockIdx.x * 256 + threadIdx.x;
    out[i] = silu_f(s[i] + r[i]);
}

// ---------------- host orchestration ------------------------------------------
struct Scratch {
    float *xz, *xi, *dbl, *dt, *y, *s, *t, *r, *r2;
    uint32_t *Ah, *Al, *Bh, *Bl;
};

static void do_split(const float* src, uint32_t* hi, uint32_t* lo, int nElem) {
    split_kernel<<<nElem / 2048, 256>>>((const float4*)src, (uint4*)hi, (uint4*)lo);
}

static void run_mamba(const float* X,
                      const float* Win, const float* convw, const float* convb,
                      const float* Wx, const float* Wdt, const float* bdt,
                      const float* Alog, const float* Dp, const float* Wout,
                      const Scratch& sc, float* out, bool x_presplit)
{
    dim3 blk(256);
    // xz = X @ Win^T   (4096 x 2048, K=1024)
    if (!x_presplit) do_split(X, sc.Ah, sc.Al, MROWS * DMDL);
    do_split(Win, sc.Bh, sc.Bl, 2 * DMDL * DMDL);
    bgemm_kernel<0><<<dim3((2 * DMDL) / 128, MROWS / 128), blk, BG_SMEM>>>(
        sc.Ah, sc.Al, sc.Bh, sc.Bl, nullptr, sc.xz, 2 * DMDL, MROWS, 2 * DMDL, DMDL);
    // xi = silu(conv(xz[:,:,:di]))
    conv_silu_kernel<<<(MROWS * DMDL) / 256, blk>>>(sc.xz, convw, convb, sc.xi);
    // dbl = xi @ Wx^T  (4096 x 68, K=1024)  — fp32 (tiny N)
    gemm_kernel<0, true><<<dim3((DTOT + TBN - 1) / TBN, MROWS / TBM), blk>>>(
        sc.xi, DMDL, 0, Wx, DMDL, 0, nullptr, sc.dbl, DTOT, 0, MROWS, DTOT, DMDL);
    // dt = softplus(dbl[:,:64] @ Wdt^T + bdt)  — fp32 (feeds exp)
    gemm_kernel<3, true><<<dim3(DMDL / TBN, MROWS / TBM), blk>>>(
        sc.dbl, DTOT, 0, Wdt, DTR, 0, bdt, sc.dt, DMDL, 0, MROWS, DMDL, DTR);
    // selective scan + skip + gate
    scan_kernel<<<BATCH * (DMDL / 256), blk>>>(sc.dt, sc.xi, sc.xz, sc.dbl, Alog, Dp, sc.y);
    // out = y @ Wout^T  (4096 x 1024, K=1024)
    do_split(sc.y, sc.Ah, sc.Al, MROWS * DMDL);
    do_split(Wout, sc.Bh, sc.Bl, DMDL * DMDL);
    bgemm_kernel<0><<<dim3(DMDL / 128, MROWS / 128), blk, BG_SMEM>>>(
        sc.Ah, sc.Al, sc.Bh, sc.Bl, nullptr, out, DMDL, MROWS, DMDL, DMDL);
}

extern "C" void kernel_launch(void* const* d_in, const int* in_sizes, int n_in,
                              void* d_out, int out_size)
{
    (void)in_sizes; (void)n_in; (void)out_size;

    const float* x        = (const float*)d_in[0];
    const float* m1_Win   = (const float*)d_in[1];
    const float* m1_convw = (const float*)d_in[2];
    const float* m1_convb = (const float*)d_in[3];
    const float* m1_Wx    = (const float*)d_in[4];
    const float* m1_Wdt   = (const float*)d_in[5];
    const float* m1_bdt   = (const float*)d_in[6];
    const float* m1_Alog  = (const float*)d_in[7];
    const float* m1_D     = (const float*)d_in[8];
    const float* m1_Wout  = (const float*)d_in[9];
    const float* m2_Win   = (const float*)d_in[10];
    const float* m2_convw = (const float*)d_in[11];
    const float* m2_convb = (const float*)d_in[12];
    const float* m2_Wx    = (const float*)d_in[13];
    const float* m2_Wdt   = (const float*)d_in[14];
    const float* m2_bdt   = (const float*)d_in[15];
    const float* m2_Alog  = (const float*)d_in[16];
    const float* m2_D     = (const float*)d_in[17];
    const float* m2_Wout  = (const float*)d_in[18];
    const float* ln1_g    = (const float*)d_in[19];
    const float* ln1_b    = (const float*)d_in[20];
    const float* ln2_g    = (const float*)d_in[21];
    const float* ln2_b    = (const float*)d_in[22];
    const float* W_mid    = (const float*)d_in[23];
    const float* W_spa    = (const float*)d_in[24];
    const float* b_spa    = (const float*)d_in[25];
    const float* W_res    = (const float*)d_in[26];
    float* out = (float*)d_out;

    // raise dynamic smem cap for bgemm (host-side attribute, no allocation)
    static bool attr_done = false;
    if (!attr_done) {
        cudaFuncSetAttribute(bgemm_kernel<0>, cudaFuncAttributeMaxDynamicSharedMemorySize, BG_SMEM);
        cudaFuncSetAttribute(bgemm_kernel<2>, cudaFuncAttributeMaxDynamicSharedMemorySize, BG_SMEM);
        attr_done = true;
    }

    Scratch sc;
    void* p;
    cudaGetSymbolAddress(&p, g_xz);  sc.xz  = (float*)p;
    cudaGetSymbolAddress(&p, g_xi);  sc.xi  = (float*)p;
    cudaGetSymbolAddress(&p, g_dbl); sc.dbl = (float*)p;
    cudaGetSymbolAddress(&p, g_dt);  sc.dt  = (float*)p;
    cudaGetSymbolAddress(&p, g_y);   sc.y   = (float*)p;
    cudaGetSymbolAddress(&p, g_s);   sc.s   = (float*)p;
    cudaGetSymbolAddress(&p, g_t);   sc.t   = (float*)p;
    cudaGetSymbolAddress(&p, g_r);   sc.r   = (float*)p;
    cudaGetSymbolAddress(&p, g_r2);  sc.r2  = (float*)p;
    cudaGetSymbolAddress(&p, g_Ah);  sc.Ah  = (uint32_t*)p;
    cudaGetSymbolAddress(&p, g_Al);  sc.Al  = (uint32_t*)p;
    cudaGetSymbolAddress(&p, g_Bh);  sc.Bh  = (uint32_t*)p;
    cudaGetSymbolAddress(&p, g_Bl);  sc.Bl  = (uint32_t*)p;

    dim3 blk(256);
    const size_t bstride = (size_t)LSEQ * DMDL;

    // ---- residual path first (reuses the x split for stage-1 Win)
    do_split(x, sc.Ah, sc.Al, MROWS * DMDL);
    do_split(W_spa, sc.Bh, sc.Bl, DMDL * DMDL);
    bgemm_kernel<2><<<dim3(DMDL / 128, MROWS / 128), blk, BG_SMEM>>>(
        sc.Ah, sc.Al, sc.Bh, sc.Bl, b_spa, sc.r, DMDL, MROWS, DMDL, DMDL);
    // r2 = silu(channel-mix with W_res)  (batched NN, HMMA)
    tgemm_kernel<1, false><<<dim3(DMDL / GBN, LSEQ / GBM, BATCH), blk>>>(
        W_res, LSEQ, 0, sc.r, DMDL, bstride, nullptr, sc.r2, DMDL, bstride,
        LSEQ, DMDL, LSEQ);

    // ---- stage 1: mamba1 -> s   (x already split in Ah/Al)
    run_mamba(x, m1_Win, m1_convw, m1_convb, m1_Wx, m1_Wdt, m1_bdt,
              m1_Alog, m1_D, m1_Wout, sc, sc.s, /*x_presplit=*/true);
    ln_kernel<<<MROWS, blk>>>(sc.s, ln1_g, ln1_b);
    // t[b,o,sp] = silu(sum_c W_mid[o,c] * s[b,c,sp])  (batched NN, HMMA)
    tgemm_kernel<1, false><<<dim3(DMDL / GBN, LSEQ / GBM, BATCH), blk>>>(
        W_mid, LSEQ, 0, sc.s, DMDL, bstride, nullptr, sc.t, DMDL, bstride,
        LSEQ, DMDL, LSEQ);

    // ---- stage 2: mamba2 -> s
    run_mamba(sc.t, m2_Win, m2_convw, m2_convb, m2_Wx, m2_Wdt, m2_bdt,
              m2_Alog, m2_D, m2_Wout, sc, sc.s, /*x_presplit=*/false);
    ln_kernel<<<MROWS, blk>>>(sc.s, ln2_g, ln2_b);

    // ---- out = silu(s + r2)
    final_kernel<<<(MROWS * DMDL) / 256, blk>>>(sc.s, sc.r2, out);
}